// round 13
// baseline (speedup 1.0000x reference)
#include <cuda_runtime.h>
#include <cuda_fp16.h>
#include <cstdint>
#include <cstddef>

// ---------------------------------------------------------------------------
// EdgeConvEncoder: 3-layer EdgeConv GNN.
//   side stream: batched counting sort of all 3 edge lists by dst (forked)
//   main stream: convert x, build all W (k-scale folded), per-layer B-resident
//                double-buffered fp16 TC GEMM + head-per-lane aggregation
//                (4 edges in flight per warp, no per-edge shuffles).
// ---------------------------------------------------------------------------

#define NN 50000
#define MAXE 500000

__device__ __half g_T[NN * 768];        // node tables (fp16), max 6*O cols
__device__ int    g_CNT3[3 * NN];       // per-layer histograms
__device__ int    g_OFF3[3 * NN];       // per-layer exclusive scans
__device__ int    g_POS3[3 * NN];       // scatter cursors
__device__ int    g_PART3[3 * 256];     // scan partials
__device__ int    g_SRCS3[3 * MAXE];    // src ids sorted by dst, per layer
__device__ float  g_X0[NN * 128];       // layer-0 output fp32 (residual)
__device__ __half g_XH[NN * 128];       // current GEMM input (fp16)
__device__ __half g_W3[3][128 * 768];   // combined weights per layer
__device__ float  g_B3[3][768];         // combined bias rows per layer

// ---------------------------------------------------------------------------
__global__ void convert_x_kernel(const float* __restrict__ x, int n) {
    int i = blockIdx.x * blockDim.x + threadIdx.x;
    if (i < n) g_XH[i] = __float2half(x[i]);
}

__global__ void zero3_kernel() {
    int i = blockIdx.x * blockDim.x + threadIdx.x;
    if (i < 3 * NN) g_CNT3[i] = 0;
}

// ---------------------------------------------------------------------------
// Batched counting sort (blockIdx.y = layer).
// ---------------------------------------------------------------------------
__global__ void hist3_kernel(const int* __restrict__ e0, const int* __restrict__ e1,
                             const int* __restrict__ e2, int E) {
    int L = blockIdx.y;
    const int* e = (L == 0) ? e0 : ((L == 1) ? e1 : e2);
    int i = blockIdx.x * blockDim.x + threadIdx.x;
    if (i < E) atomicAdd(&g_CNT3[L * NN + e[E + i]], 1);
}

__global__ void scan1_kernel() {
    int L = blockIdx.y;
    __shared__ int s[256];
    int t = threadIdx.x;
    int i = blockIdx.x * 256 + t;
    int v = (i < NN) ? g_CNT3[L * NN + i] : 0;
    s[t] = v;
    __syncthreads();
#pragma unroll
    for (int d = 1; d < 256; d <<= 1) {
        int x = (t >= d) ? s[t - d] : 0;
        __syncthreads();
        s[t] += x;
        __syncthreads();
    }
    if (i < NN) g_OFF3[L * NN + i] = s[t] - v;
    if (t == 255) g_PART3[L * 256 + blockIdx.x] = s[255];
}

__global__ void scan2_kernel(int P) {
    int L = blockIdx.y;
    __shared__ int s[256];
    int t = threadIdx.x;
    int v = (t < P) ? g_PART3[L * 256 + t] : 0;
    s[t] = v;
    __syncthreads();
#pragma unroll
    for (int d = 1; d < 256; d <<= 1) {
        int x = (t >= d) ? s[t - d] : 0;
        __syncthreads();
        s[t] += x;
        __syncthreads();
    }
    if (t < P) g_PART3[L * 256 + t] = s[t] - v;
}

__global__ void scan3_kernel() {
    int L = blockIdx.y;
    int i = blockIdx.x * 256 + threadIdx.x;
    if (i < NN) {
        int o = g_OFF3[L * NN + i] + g_PART3[L * 256 + blockIdx.x];
        g_OFF3[L * NN + i] = o;
        g_POS3[L * NN + i] = o;
    }
}

__global__ void scatter3_kernel(const int* __restrict__ e0, const int* __restrict__ e1,
                                const int* __restrict__ e2, int E) {
    int L = blockIdx.y;
    const int* e = (L == 0) ? e0 : ((L == 1) ? e1 : e2);
    int i = blockIdx.x * blockDim.x + threadIdx.x;
    if (i < E) {
        int src = e[i];
        int dst = e[E + i];
        int pos = atomicAdd(&g_POS3[L * NN + dst], 1);
        g_SRCS3[L * MAXE + pos] = src;
    }
}

// ---------------------------------------------------------------------------
// Build combined fp16 weight matrix for layer L; 1/sqrt(hs) folded into k:
// cols [0,O)=wq diff [O,2O)=wk diff * ks [2O,3O)=wv diff
// cols [3O,4O)=wq_bot [4O,5O)=wk_bot * ks [5O,6O)=wv_bot
// bias row: bq | bk*ks | bv  (then zeros)
// ---------------------------------------------------------------------------
__global__ void build_w_kernel(const float* __restrict__ wq, const float* __restrict__ wk,
                               const float* __restrict__ wv, const float* __restrict__ bq,
                               const float* __restrict__ bk, const float* __restrict__ bv,
                               int C, int O, int L, float ks) {
    int M = 6 * O;
    int idx = blockIdx.x * blockDim.x + threadIdx.x;
    if (idx < C * M) {
        int c = idx / M;
        int m = idx - c * M;
        int which = m / O;
        int o = m - which * O;
        int qkv = which % 3;
        const float* w = (qkv == 0) ? wq : ((qkv == 1) ? wk : wv);
        float top = w[c * O + o];
        float bot = w[(C + c) * O + o];
        float val = (which < 3) ? (top - bot) : bot;
        if (qkv == 1) val *= ks;
        g_W3[L][idx] = __float2half(val);
    }
    if (idx < M) {
        int which = idx / O;
        int o = idx - which * O;
        float b = 0.f;
        if (which == 0) b = bq[o];
        else if (which == 1) b = bk[o] * ks;
        else if (which == 2) b = bv[o];
        g_B3[L][idx] = b;
    }
}

// ---------------------------------------------------------------------------
// B-resident + A double-buffered fp16 TC GEMM:
//   g_T[N x M] = g_XH[N x K] @ g_W3[L][K x M] + g_B3[L]
// ---------------------------------------------------------------------------
__device__ __forceinline__ uint32_t smem_u32(const void* p) {
    return (uint32_t)__cvta_generic_to_shared(p);
}
#define CP_ASYNC16(dst, src) \
    asm volatile("cp.async.cg.shared.global [%0], [%1], 16;" :: "r"(dst), "l"(src))
#define CP_COMMIT() asm volatile("cp.async.commit_group;" ::: "memory")
#define CP_WAIT(n)  asm volatile("cp.async.wait_group %0;" :: "n"(n) : "memory")

template <int K>
__global__ __launch_bounds__(256) void gemm_v3_kernel(const __half* __restrict__ A,
                                                      int N, int M, int L) {
    constexpr int AS = K + 8;
    constexpr int BS = 136;
    extern __shared__ __align__(16) char smem_raw[];
    __half* Asm0 = (__half*)smem_raw;
    __half* Asm1 = (__half*)(smem_raw + 128 * AS * 2);
    __half* Bsm  = (__half*)(smem_raw + 2 * 128 * AS * 2);

    int tid  = threadIdx.x;
    int lane = tid & 31;
    int wid  = tid >> 5;
    int warp_m = wid >> 2;
    int warp_n = wid & 3;
    int col0 = blockIdx.x * 128;
    const __half* W = g_W3[L];

    {
        constexpr int CH = K * 128 / 8;
#pragma unroll
        for (int u = 0; u < CH / 256; u++) {
            int idx = tid + u * 256;
            int r   = idx >> 4;
            int c   = (idx & 15) << 3;
            CP_ASYNC16(smem_u32(&Bsm[r * BS + c]),
                       W + (size_t)r * M + col0 + c);
        }
        CP_COMMIT();
    }

    int g  = lane >> 2;
    int t4 = lane & 3;
    float bias_x[4], bias_y[4];
#pragma unroll
    for (int nt = 0; nt < 4; nt++) {
        int col = col0 + warp_n * 32 + nt * 8 + t4 * 2;
        bias_x[nt] = g_B3[L][col];
        bias_y[nt] = g_B3[L][col + 1];
    }

    auto load_a = [&](__half* dst, int rt) {
        int row0 = rt << 7;
        constexpr int CHA = 128 * K / 8;
        constexpr int CPR = K / 8;
#pragma unroll
        for (int u = 0; u < CHA / 256; u++) {
            int idx = tid + u * 256;
            int r   = idx / CPR;
            int c   = (idx % CPR) << 3;
            if (row0 + r < N) {
                CP_ASYNC16(smem_u32(&dst[r * AS + c]),
                           A + (size_t)(row0 + r) * K + c);
            }
        }
        CP_COMMIT();
    };

    int nTiles = (N + 127) >> 7;
    int rt0 = blockIdx.y;
    if (rt0 >= nTiles) return;
    load_a(Asm0, rt0);

    int it = 0;
    for (int rt = rt0; rt < nTiles; rt += gridDim.y, it++) {
        __half* Acur = (it & 1) ? Asm1 : Asm0;
        __half* Anxt = (it & 1) ? Asm0 : Asm1;
        int rtn = rt + gridDim.y;
        if (rtn < nTiles) {
            load_a(Anxt, rtn);
            CP_WAIT(1);
        } else {
            CP_WAIT(0);
        }
        __syncthreads();

        int row0 = rt << 7;
        float acc[4][4][4];
#pragma unroll
        for (int mt = 0; mt < 4; mt++)
#pragma unroll
            for (int nt = 0; nt < 4; nt++)
#pragma unroll
                for (int i = 0; i < 4; i++) acc[mt][nt][i] = 0.f;

        int m0 = warp_m * 64;
        int n0 = warp_n * 32;
#pragma unroll
        for (int kk = 0; kk < K; kk += 16) {
            uint32_t a[4][4];
#pragma unroll
            for (int mt = 0; mt < 4; mt++) {
                uint32_t addr = smem_u32(&Acur[(m0 + mt * 16 + (lane & 15)) * AS +
                                               kk + (lane >> 4) * 8]);
                asm volatile("ldmatrix.sync.aligned.m8n8.x4.shared.b16 {%0,%1,%2,%3}, [%4];"
                             : "=r"(a[mt][0]), "=r"(a[mt][1]), "=r"(a[mt][2]), "=r"(a[mt][3])
                             : "r"(addr));
            }
            uint32_t b[4][2];
#pragma unroll
            for (int np = 0; np < 2; np++) {
                uint32_t addr = smem_u32(&Bsm[(kk + (lane & 15)) * BS +
                                              n0 + np * 16 + (lane >> 4) * 8]);
                uint32_t r0, r1, r2, r3;
                asm volatile("ldmatrix.sync.aligned.m8n8.x4.trans.shared.b16 {%0,%1,%2,%3}, [%4];"
                             : "=r"(r0), "=r"(r1), "=r"(r2), "=r"(r3)
                             : "r"(addr));
                b[np * 2 + 0][0] = r0; b[np * 2 + 0][1] = r1;
                b[np * 2 + 1][0] = r2; b[np * 2 + 1][1] = r3;
            }
#pragma unroll
            for (int mt = 0; mt < 4; mt++)
#pragma unroll
                for (int nt = 0; nt < 4; nt++) {
                    asm volatile(
                        "mma.sync.aligned.m16n8k16.row.col.f32.f16.f16.f32 "
                        "{%0,%1,%2,%3}, {%4,%5,%6,%7}, {%8,%9}, {%0,%1,%2,%3};"
                        : "+f"(acc[mt][nt][0]), "+f"(acc[mt][nt][1]),
                          "+f"(acc[mt][nt][2]), "+f"(acc[mt][nt][3])
                        : "r"(a[mt][0]), "r"(a[mt][1]), "r"(a[mt][2]), "r"(a[mt][3]),
                          "r"(b[nt][0]), "r"(b[nt][1]));
                }
        }

#pragma unroll
        for (int mt = 0; mt < 4; mt++) {
#pragma unroll
            for (int nt = 0; nt < 4; nt++) {
                int col = col0 + warp_n * 32 + nt * 8 + t4 * 2;
#pragma unroll
                for (int h = 0; h < 2; h++) {
                    int r = row0 + warp_m * 64 + mt * 16 + g + h * 8;
                    if (r < N) {
                        __half2 o = __floats2half2_rn(acc[mt][nt][h * 2 + 0] + bias_x[nt],
                                                      acc[mt][nt][h * 2 + 1] + bias_y[nt]);
                        *(__half2*)(g_T + (size_t)r * M + col) = o;
                    }
                }
            }
        }
        __syncthreads();
    }
}

// ---------------------------------------------------------------------------
// Head-per-lane aggregation: warp per node; lane owns head h=lane&7;
// subgroup g=lane>>3 processes edge j+g (4 edges in flight, no per-edge shfl).
// Scale already folded into k at build time.
//   MODE 0: X0 = relu(mean), XH = half(X0)   (O=128)
//   MODE 1: XH = half(relu(mean))            (O=64)
//   MODE 2: out = relu(mean + X0)            (O=128)
// ---------------------------------------------------------------------------
template <int H2>
__device__ __forceinline__ void ldreg(const __half* p, __half2* r) {
#pragma unroll
    for (int c = 0; c < H2 / 4; c++) {
        uint4 raw = *(const uint4*)(p + c * 8);
        r[c * 4 + 0] = *((__half2*)&raw.x);
        r[c * 4 + 1] = *((__half2*)&raw.y);
        r[c * 4 + 2] = *((__half2*)&raw.z);
        r[c * 4 + 3] = *((__half2*)&raw.w);
    }
}

template <int O, int HS, int MODE>
__global__ __launch_bounds__(128) void agg2_kernel(float* __restrict__ out, int N, int L) {
    int n = (blockIdx.x * 128 + threadIdx.x) >> 5;
    if (n >= N) return;
    int lane = threadIdx.x & 31;
    int g = lane >> 3;       // subgroup: which of 4 concurrent edges
    int h = lane & 7;        // head owned by this lane
    constexpr int H2 = HS / 2;
    constexpr int STRIDE = 6 * O;
    int laneoff = h * HS;

    int cnt = g_CNT3[L * NN + n];
    float res[HS];
#pragma unroll
    for (int u = 0; u < HS; u++) res[u] = 0.f;

    if (cnt > 0) {
        const __half* D = g_T + (size_t)n * STRIDE + laneoff;
        __half2 dq2[H2], dk2[H2], dv2[H2];
        ldreg<H2>(D, dq2);
        ldreg<H2>(D + O, dk2);
        ldreg<H2>(D + 2 * O, dv2);

        const int* srcs = g_SRCS3 + L * MAXE;
        int off = g_OFF3[L * NN + n];

        for (int j = 0; j < cnt; j += 4) {
            int e = j + g;
            int ee = (e < cnt) ? e : (cnt - 1);
            int src = srcs[off + ee];
            const __half* S = g_T + (size_t)src * STRIDE + 3 * O + laneoff;
            __half2 sq2[H2], sk2[H2], sv2[H2];
            ldreg<H2>(S, sq2);
            ldreg<H2>(S + O, sk2);
            ldreg<H2>(S + 2 * O, sv2);

            int dd = n - src;
            if (dd < 0) dd = -dd;
            float ew = (dd > 8) ? 1.0f : ((dd == 8) ? 0.0f : -1.0f);
            if (e >= cnt) ew = 0.0f;

            float tmp[HS];
            float ssum = 0.f;
#pragma unroll
            for (int u = 0; u < H2; u++) {
                float2 q = __half22float2(__hadd2(dq2[u], sq2[u]));
                float2 k = __half22float2(__hadd2(dk2[u], sk2[u]));
                float2 v = __half22float2(__hadd2(dv2[u], sv2[u]));
                float p0 = __expf(q.x * k.x);
                float p1 = __expf(q.y * k.y);
                ssum += p0 + p1;
                tmp[2 * u]     = p0 * v.x;
                tmp[2 * u + 1] = p1 * v.y;
            }
            float w = __fdividef(ew, ssum);
#pragma unroll
            for (int u = 0; u < HS; u++)
                res[u] = fmaf(tmp[u], w, res[u]);
        }
        float invc = __fdividef(1.0f, (float)cnt);
#pragma unroll
        for (int u = 0; u < HS; u++) res[u] *= invc;
    }

    // combine the 4 edge-subgroups (lanes h, h+8, h+16, h+24)
#pragma unroll
    for (int u = 0; u < HS; u++) {
        res[u] += __shfl_xor_sync(0xffffffffu, res[u], 8);
        res[u] += __shfl_xor_sync(0xffffffffu, res[u], 16);
    }

    // each lane writes HS/4 channels at h*HS + g*(HS/4)
    constexpr int CPW = HS / 4;
    int chan = h * HS + g * CPW;

    if constexpr (MODE == 0) {
        float v0 = fmaxf(res[g * 4 + 0], 0.f);
        float v1 = fmaxf(res[g * 4 + 1], 0.f);
        float v2 = fmaxf(res[g * 4 + 2], 0.f);
        float v3 = fmaxf(res[g * 4 + 3], 0.f);
        *(float4*)(g_X0 + (size_t)n * 128 + chan) = make_float4(v0, v1, v2, v3);
        __half2 hh[2];
        hh[0] = __floats2half2_rn(v0, v1);
        hh[1] = __floats2half2_rn(v2, v3);
        *(uint2*)(g_XH + (size_t)n * 128 + chan) = *(uint2*)hh;
    } else if constexpr (MODE == 1) {
        __half2 hh = __floats2half2_rn(fmaxf(res[g * 2 + 0], 0.f),
                                       fmaxf(res[g * 2 + 1], 0.f));
        *(__half2*)(g_XH + (size_t)n * 64 + chan) = hh;
    } else {
        float4 x0 = *(const float4*)(g_X0 + (size_t)n * 128 + chan);
        float4 o;
        o.x = fmaxf(res[g * 4 + 0] + x0.x, 0.f);
        o.y = fmaxf(res[g * 4 + 1] + x0.y, 0.f);
        o.z = fmaxf(res[g * 4 + 2] + x0.z, 0.f);
        o.w = fmaxf(res[g * 4 + 3] + x0.w, 0.f);
        *(float4*)(out + (size_t)n * 128 + chan) = o;
    }
}

// ---------------------------------------------------------------------------
extern "C" void kernel_launch(void* const* d_in, const int* in_sizes, int n_in,
                              void* d_out, int out_size) {
    const float* x   = (const float*)d_in[0];
    const int*   e0  = (const int*)d_in[1];
    const int*   e1  = (const int*)d_in[2];
    const int*   e2  = (const int*)d_in[3];
    // d_in[4] = batch (unused)
    const float* wq0 = (const float*)d_in[5],  *bq0 = (const float*)d_in[6];
    const float* wk0 = (const float*)d_in[7],  *bk0 = (const float*)d_in[8];
    const float* wv0 = (const float*)d_in[9],  *bv0 = (const float*)d_in[10];
    const float* wq1 = (const float*)d_in[11], *bq1 = (const float*)d_in[12];
    const float* wk1 = (const float*)d_in[13], *bk1 = (const float*)d_in[14];
    const float* wv1 = (const float*)d_in[15], *bv1 = (const float*)d_in[16];
    const float* wq2 = (const float*)d_in[17], *bq2 = (const float*)d_in[18];
    const float* wk2 = (const float*)d_in[19], *bk2 = (const float*)d_in[20];
    const float* wv2 = (const float*)d_in[21], *bv2 = (const float*)d_in[22];
    float* out = (float*)d_out;

    int N  = in_sizes[0] / 128;   // 50000
    int E  = in_sizes[1] / 2;     // 500000

    __half* pXH = nullptr;
    cudaGetSymbolAddress((void**)&pXH, g_XH);

    constexpr int SMEM128 = 2 * 128 * 136 * 2 + 128 * 136 * 2;  // 104448
    constexpr int SMEM64  = 2 * 128 * 72 * 2  + 64 * 136 * 2;   // 54272

    const float KS16 = 0.25f;                 // 1/sqrt(16)
    const float KS8  = 0.35355339059327373f;  // 1/sqrt(8)

    static cudaStream_t s2 = nullptr;
    static cudaEvent_t evFork = nullptr, evJoin = nullptr;
    if (s2 == nullptr) {
        cudaFuncSetAttribute(gemm_v3_kernel<128>,
                             cudaFuncAttributeMaxDynamicSharedMemorySize, SMEM128);
        cudaFuncSetAttribute(gemm_v3_kernel<64>,
                             cudaFuncAttributeMaxDynamicSharedMemorySize, SMEM64);
        cudaStreamCreateWithFlags(&s2, cudaStreamNonBlocking);
        cudaEventCreateWithFlags(&evFork, cudaEventDisableTiming);
        cudaEventCreateWithFlags(&evJoin, cudaEventDisableTiming);
    }

    // ---- fork: edge sorts on side stream ----
    cudaEventRecord(evFork, 0);
    cudaStreamWaitEvent(s2, evFork, 0);
    {
        dim3 ge((E + 255) / 256, 3);
        dim3 gn((NN + 255) / 256, 3);
        zero3_kernel<<<(3 * NN + 255) / 256, 256, 0, s2>>>();
        hist3_kernel<<<ge, 256, 0, s2>>>(e0, e1, e2, E);
        scan1_kernel<<<gn, 256, 0, s2>>>();
        scan2_kernel<<<dim3(1, 3), 256, 0, s2>>>((NN + 255) / 256);
        scan3_kernel<<<gn, 256, 0, s2>>>();
        scatter3_kernel<<<ge, 256, 0, s2>>>(e0, e1, e2, E);
    }
    cudaEventRecord(evJoin, s2);

    // ---- main stream: convert + build all weights ----
    convert_x_kernel<<<(N * 128 + 255) / 256, 256>>>(x, N * 128);
    build_w_kernel<<<(128 * 768 + 255) / 256, 256>>>(wq0, wk0, wv0, bq0, bk0, bv0, 128, 128, 0, KS16);
    build_w_kernel<<<(128 * 384 + 255) / 256, 256>>>(wq1, wk1, wv1, bq1, bk1, bv1, 128, 64, 1, KS8);
    build_w_kernel<<<(64 * 768 + 255) / 256, 256>>>(wq2, wk2, wv2, bq2, bk2, bv2, 64, 128, 2, KS16);

    int aggGrid = (N + 3) / 4;   // 128 threads = 4 warps = 4 nodes per block

    // ---- Layer 0: C=128, O=128, M=768 ----
    gemm_v3_kernel<128><<<dim3(6, 49), 256, SMEM128>>>(pXH, N, 768, 0);
    cudaStreamWaitEvent(0, evJoin, 0);
    agg2_kernel<128, 16, 0><<<aggGrid, 128>>>(nullptr, N, 0);

    // ---- Layer 1: C=128, O=64, M=384 ----
    gemm_v3_kernel<128><<<dim3(3, 98), 256, SMEM128>>>(pXH, N, 384, 1);
    agg2_kernel<64, 8, 1><<<aggGrid, 128>>>(nullptr, N, 1);

    // ---- Layer 2: C=64, O=128, M=768 ----
    gemm_v3_kernel<64><<<dim3(6, 49), 256, SMEM64>>>(pXH, N, 768, 2);
    agg2_kernel<128, 16, 2><<<aggGrid, 128>>>(out, N, 2);
}

// round 15
// speedup vs baseline: 1.0568x; 1.0568x over previous
#include <cuda_runtime.h>
#include <cuda_fp16.h>
#include <cstdint>
#include <cstddef>

// ---------------------------------------------------------------------------
// EdgeConvEncoder: 3-layer EdgeConv GNN.
//   side stream: batched counting sort of all 3 edge lists by dst (forked)
//   main stream: convert x, build all W (k-scale folded), per-layer B-resident
//                double-buffered fp16 TC GEMM + warp-per-node aggregation
//                (channel-per-lane, 2-edge unroll), fused finalize.
// ---------------------------------------------------------------------------

#define NN 50000
#define MAXE 500000

__device__ __half g_T[NN * 768];        // node tables (fp16), max 6*O cols
__device__ int    g_CNT3[3 * NN];       // per-layer histograms
__device__ int    g_OFF3[3 * NN];       // per-layer exclusive scans
__device__ int    g_POS3[3 * NN];       // scatter cursors
__device__ int    g_PART3[3 * 256];     // scan partials
__device__ int    g_SRCS3[3 * MAXE];    // src ids sorted by dst, per layer
__device__ float  g_X0[NN * 128];       // layer-0 output fp32 (residual)
__device__ __half g_XH[NN * 128];       // current GEMM input (fp16)
__device__ __half g_W3[3][128 * 768];   // combined weights per layer
__device__ float  g_B3[3][768];         // combined bias rows per layer

// ---------------------------------------------------------------------------
__global__ void convert_x_kernel(const float* __restrict__ x, int n) {
    int i = blockIdx.x * blockDim.x + threadIdx.x;
    if (i < n) g_XH[i] = __float2half(x[i]);
}

__global__ void zero3_kernel() {
    int i = blockIdx.x * blockDim.x + threadIdx.x;
    if (i < 3 * NN) g_CNT3[i] = 0;
}

// ---------------------------------------------------------------------------
// Batched counting sort (blockIdx.y = layer).
// ---------------------------------------------------------------------------
__global__ void hist3_kernel(const int* __restrict__ e0, const int* __restrict__ e1,
                             const int* __restrict__ e2, int E) {
    int L = blockIdx.y;
    const int* e = (L == 0) ? e0 : ((L == 1) ? e1 : e2);
    int i = blockIdx.x * blockDim.x + threadIdx.x;
    if (i < E) atomicAdd(&g_CNT3[L * NN + e[E + i]], 1);
}

__global__ void scan1_kernel() {
    int L = blockIdx.y;
    __shared__ int s[256];
    int t = threadIdx.x;
    int i = blockIdx.x * 256 + t;
    int v = (i < NN) ? g_CNT3[L * NN + i] : 0;
    s[t] = v;
    __syncthreads();
#pragma unroll
    for (int d = 1; d < 256; d <<= 1) {
        int x = (t >= d) ? s[t - d] : 0;
        __syncthreads();
        s[t] += x;
        __syncthreads();
    }
    if (i < NN) g_OFF3[L * NN + i] = s[t] - v;
    if (t == 255) g_PART3[L * 256 + blockIdx.x] = s[255];
}

__global__ void scan2_kernel(int P) {
    int L = blockIdx.y;
    __shared__ int s[256];
    int t = threadIdx.x;
    int v = (t < P) ? g_PART3[L * 256 + t] : 0;
    s[t] = v;
    __syncthreads();
#pragma unroll
    for (int d = 1; d < 256; d <<= 1) {
        int x = (t >= d) ? s[t - d] : 0;
        __syncthreads();
        s[t] += x;
        __syncthreads();
    }
    if (t < P) g_PART3[L * 256 + t] = s[t] - v;
}

__global__ void scan3_kernel() {
    int L = blockIdx.y;
    int i = blockIdx.x * 256 + threadIdx.x;
    if (i < NN) {
        int o = g_OFF3[L * NN + i] + g_PART3[L * 256 + blockIdx.x];
        g_OFF3[L * NN + i] = o;
        g_POS3[L * NN + i] = o;
    }
}

__global__ void scatter3_kernel(const int* __restrict__ e0, const int* __restrict__ e1,
                                const int* __restrict__ e2, int E) {
    int L = blockIdx.y;
    const int* e = (L == 0) ? e0 : ((L == 1) ? e1 : e2);
    int i = blockIdx.x * blockDim.x + threadIdx.x;
    if (i < E) {
        int src = e[i];
        int dst = e[E + i];
        int pos = atomicAdd(&g_POS3[L * NN + dst], 1);
        g_SRCS3[L * MAXE + pos] = src;
    }
}

// ---------------------------------------------------------------------------
// Build combined fp16 weight matrix for layer L; 1/sqrt(hs) folded into k:
// cols [0,O)=wq diff [O,2O)=wk diff * ks [2O,3O)=wv diff
// cols [3O,4O)=wq_bot [4O,5O)=wk_bot * ks [5O,6O)=wv_bot
// bias row: bq | bk*ks | bv
// ---------------------------------------------------------------------------
__global__ void build_w_kernel(const float* __restrict__ wq, const float* __restrict__ wk,
                               const float* __restrict__ wv, const float* __restrict__ bq,
                               const float* __restrict__ bk, const float* __restrict__ bv,
                               int C, int O, int L, float ks) {
    int M = 6 * O;
    int idx = blockIdx.x * blockDim.x + threadIdx.x;
    if (idx < C * M) {
        int c = idx / M;
        int m = idx - c * M;
        int which = m / O;
        int o = m - which * O;
        int qkv = which % 3;
        const float* w = (qkv == 0) ? wq : ((qkv == 1) ? wk : wv);
        float top = w[c * O + o];
        float bot = w[(C + c) * O + o];
        float val = (which < 3) ? (top - bot) : bot;
        if (qkv == 1) val *= ks;
        g_W3[L][idx] = __float2half(val);
    }
    if (idx < M) {
        int which = idx / O;
        int o = idx - which * O;
        float b = 0.f;
        if (which == 0) b = bq[o];
        else if (which == 1) b = bk[o] * ks;
        else if (which == 2) b = bv[o];
        g_B3[L][idx] = b;
    }
}

// ---------------------------------------------------------------------------
// B-resident + A double-buffered fp16 TC GEMM:
//   g_T[N x M] = g_XH[N x K] @ g_W3[L][K x M] + g_B3[L]
// ---------------------------------------------------------------------------
__device__ __forceinline__ uint32_t smem_u32(const void* p) {
    return (uint32_t)__cvta_generic_to_shared(p);
}
#define CP_ASYNC16(dst, src) \
    asm volatile("cp.async.cg.shared.global [%0], [%1], 16;" :: "r"(dst), "l"(src))
#define CP_COMMIT() asm volatile("cp.async.commit_group;" ::: "memory")
#define CP_WAIT(n)  asm volatile("cp.async.wait_group %0;" :: "n"(n) : "memory")

template <int K>
__global__ __launch_bounds__(256) void gemm_v3_kernel(const __half* __restrict__ A,
                                                      int N, int M, int L) {
    constexpr int AS = K + 8;
    constexpr int BS = 136;
    extern __shared__ __align__(16) char smem_raw[];
    __half* Asm0 = (__half*)smem_raw;
    __half* Asm1 = (__half*)(smem_raw + 128 * AS * 2);
    __half* Bsm  = (__half*)(smem_raw + 2 * 128 * AS * 2);

    int tid  = threadIdx.x;
    int lane = tid & 31;
    int wid  = tid >> 5;
    int warp_m = wid >> 2;
    int warp_n = wid & 3;
    int col0 = blockIdx.x * 128;
    const __half* W = g_W3[L];

    {
        constexpr int CH = K * 128 / 8;
#pragma unroll
        for (int u = 0; u < CH / 256; u++) {
            int idx = tid + u * 256;
            int r   = idx >> 4;
            int c   = (idx & 15) << 3;
            CP_ASYNC16(smem_u32(&Bsm[r * BS + c]),
                       W + (size_t)r * M + col0 + c);
        }
        CP_COMMIT();
    }

    int g  = lane >> 2;
    int t4 = lane & 3;
    float bias_x[4], bias_y[4];
#pragma unroll
    for (int nt = 0; nt < 4; nt++) {
        int col = col0 + warp_n * 32 + nt * 8 + t4 * 2;
        bias_x[nt] = g_B3[L][col];
        bias_y[nt] = g_B3[L][col + 1];
    }

    auto load_a = [&](__half* dst, int rt) {
        int row0 = rt << 7;
        constexpr int CHA = 128 * K / 8;
        constexpr int CPR = K / 8;
#pragma unroll
        for (int u = 0; u < CHA / 256; u++) {
            int idx = tid + u * 256;
            int r   = idx / CPR;
            int c   = (idx % CPR) << 3;
            if (row0 + r < N) {
                CP_ASYNC16(smem_u32(&dst[r * AS + c]),
                           A + (size_t)(row0 + r) * K + c);
            }
        }
        CP_COMMIT();
    };

    int nTiles = (N + 127) >> 7;
    int rt0 = blockIdx.y;
    if (rt0 >= nTiles) return;
    load_a(Asm0, rt0);

    int it = 0;
    for (int rt = rt0; rt < nTiles; rt += gridDim.y, it++) {
        __half* Acur = (it & 1) ? Asm1 : Asm0;
        __half* Anxt = (it & 1) ? Asm0 : Asm1;
        int rtn = rt + gridDim.y;
        if (rtn < nTiles) {
            load_a(Anxt, rtn);
            CP_WAIT(1);
        } else {
            CP_WAIT(0);
        }
        __syncthreads();

        int row0 = rt << 7;
        float acc[4][4][4];
#pragma unroll
        for (int mt = 0; mt < 4; mt++)
#pragma unroll
            for (int nt = 0; nt < 4; nt++)
#pragma unroll
                for (int i = 0; i < 4; i++) acc[mt][nt][i] = 0.f;

        int m0 = warp_m * 64;
        int n0 = warp_n * 32;
#pragma unroll
        for (int kk = 0; kk < K; kk += 16) {
            uint32_t a[4][4];
#pragma unroll
            for (int mt = 0; mt < 4; mt++) {
                uint32_t addr = smem_u32(&Acur[(m0 + mt * 16 + (lane & 15)) * AS +
                                               kk + (lane >> 4) * 8]);
                asm volatile("ldmatrix.sync.aligned.m8n8.x4.shared.b16 {%0,%1,%2,%3}, [%4];"
                             : "=r"(a[mt][0]), "=r"(a[mt][1]), "=r"(a[mt][2]), "=r"(a[mt][3])
                             : "r"(addr));
            }
            uint32_t b[4][2];
#pragma unroll
            for (int np = 0; np < 2; np++) {
                uint32_t addr = smem_u32(&Bsm[(kk + (lane & 15)) * BS +
                                              n0 + np * 16 + (lane >> 4) * 8]);
                uint32_t r0, r1, r2, r3;
                asm volatile("ldmatrix.sync.aligned.m8n8.x4.trans.shared.b16 {%0,%1,%2,%3}, [%4];"
                             : "=r"(r0), "=r"(r1), "=r"(r2), "=r"(r3)
                             : "r"(addr));
                b[np * 2 + 0][0] = r0; b[np * 2 + 0][1] = r1;
                b[np * 2 + 1][0] = r2; b[np * 2 + 1][1] = r3;
            }
#pragma unroll
            for (int mt = 0; mt < 4; mt++)
#pragma unroll
                for (int nt = 0; nt < 4; nt++) {
                    asm volatile(
                        "mma.sync.aligned.m16n8k16.row.col.f32.f16.f16.f32 "
                        "{%0,%1,%2,%3}, {%4,%5,%6,%7}, {%8,%9}, {%0,%1,%2,%3};"
                        : "+f"(acc[mt][nt][0]), "+f"(acc[mt][nt][1]),
                          "+f"(acc[mt][nt][2]), "+f"(acc[mt][nt][3])
                        : "r"(a[mt][0]), "r"(a[mt][1]), "r"(a[mt][2]), "r"(a[mt][3]),
                          "r"(b[nt][0]), "r"(b[nt][1]));
                }
        }

#pragma unroll
        for (int mt = 0; mt < 4; mt++) {
#pragma unroll
            for (int nt = 0; nt < 4; nt++) {
                int col = col0 + warp_n * 32 + nt * 8 + t4 * 2;
#pragma unroll
                for (int h = 0; h < 2; h++) {
                    int r = row0 + warp_m * 64 + mt * 16 + g + h * 8;
                    if (r < N) {
                        __half2 o = __floats2half2_rn(acc[mt][nt][h * 2 + 0] + bias_x[nt],
                                                      acc[mt][nt][h * 2 + 1] + bias_y[nt]);
                        *(__half2*)(g_T + (size_t)r * M + col) = o;
                    }
                }
            }
        }
        __syncthreads();
    }
}

// ---------------------------------------------------------------------------
// Aggregate: one warp per dst node, channel-per-lane (V=O/32), 2-edge unroll.
// k-scale folded into W at build time (no per-edge scale mul).
//   MODE 0: X0 = relu(mean), XH = half(X0)   (O=128)
//   MODE 1: XH = half(relu(mean))            (O=64)
//   MODE 2: out = relu(mean + X0)            (O=128)
// ---------------------------------------------------------------------------
template <int O, int HS, int MODE>
__global__ __launch_bounds__(256) void agg_kernel(float* __restrict__ out, int N, int L) {
    int n = (blockIdx.x * 256 + threadIdx.x) >> 5;
    if (n >= N) return;
    int lane = threadIdx.x & 31;
    constexpr int V = O / 32;
    int base = lane * V;

    int cnt = g_CNT3[L * NN + n];
    float res[V];
#pragma unroll
    for (int u = 0; u < V; u++) res[u] = 0.f;

    if (cnt > 0) {
        constexpr int STRIDE = 6 * O;
        const int* srcs = g_SRCS3 + L * MAXE;
        const __half* D = g_T + (size_t)n * STRIDE;
        auto ld4 = [](const __half* p, float* o) {
            uint2 raw = *(const uint2*)p;
            __half2* h = (__half2*)&raw;
            float2 a = __half22float2(h[0]), b = __half22float2(h[1]);
            o[0] = a.x; o[1] = a.y; o[2] = b.x; o[3] = b.y;
        };
        auto ld2 = [](const __half* p, float* o) {
            float2 a = __half22float2(*(const __half2*)p);
            o[0] = a.x; o[1] = a.y;
        };
        float dq[V], dk[V], dv[V];
        if constexpr (V == 4) {
            ld4(D + base, dq); ld4(D + O + base, dk); ld4(D + 2 * O + base, dv);
        } else {
            ld2(D + base, dq); ld2(D + O + base, dk); ld2(D + 2 * O + base, dv);
        }

        int off = g_OFF3[L * NN + n];

        auto edge_contrib = [&](int src, const float* sq, const float* sk,
                                const float* sv) {
            int dd = n - src;
            if (dd < 0) dd = -dd;
            float ew = (dd > 8) ? 1.0f : ((dd == 8) ? 0.0f : -1.0f);
            float p[V];
            float ssum = 0.f;
#pragma unroll
            for (int u = 0; u < V; u++) {
                float t = (dq[u] + sq[u]) * (dk[u] + sk[u]);   // scale folded into k
                p[u] = __expf(t);
                ssum += p[u];
            }
            ssum += __shfl_xor_sync(0xffffffffu, ssum, 1);
            ssum += __shfl_xor_sync(0xffffffffu, ssum, 2);
            float w = __fdividef(ew, ssum);
#pragma unroll
            for (int u = 0; u < V; u++)
                res[u] = fmaf(p[u] * (dv[u] + sv[u]), w, res[u]);
        };

        int j = 0;
        for (; j + 2 <= cnt; j += 2) {
            int s0 = srcs[off + j];
            int s1 = srcs[off + j + 1];
            const __half* S0 = g_T + (size_t)s0 * STRIDE + 3 * O;
            const __half* S1 = g_T + (size_t)s1 * STRIDE + 3 * O;
            float aq[V], ak[V], av[V], bq[V], bk[V], bv[V];
            if constexpr (V == 4) {
                ld4(S0 + base, aq); ld4(S0 + O + base, ak); ld4(S0 + 2 * O + base, av);
                ld4(S1 + base, bq); ld4(S1 + O + base, bk); ld4(S1 + 2 * O + base, bv);
            } else {
                ld2(S0 + base, aq); ld2(S0 + O + base, ak); ld2(S0 + 2 * O + base, av);
                ld2(S1 + base, bq); ld2(S1 + O + base, bk); ld2(S1 + 2 * O + base, bv);
            }
            edge_contrib(s0, aq, ak, av);
            edge_contrib(s1, bq, bk, bv);
        }
        if (j < cnt) {
            int s0 = srcs[off + j];
            const __half* S0 = g_T + (size_t)s0 * STRIDE + 3 * O;
            float aq[V], ak[V], av[V];
            if constexpr (V == 4) {
                ld4(S0 + base, aq); ld4(S0 + O + base, ak); ld4(S0 + 2 * O + base, av);
            } else {
                ld2(S0 + base, aq); ld2(S0 + O + base, ak); ld2(S0 + 2 * O + base, av);
            }
            edge_contrib(s0, aq, ak, av);
        }
        float invc = __fdividef(1.0f, (float)cnt);
#pragma unroll
        for (int u = 0; u < V; u++) res[u] *= invc;
    }

    if constexpr (MODE == 0) {
        float v[4];
#pragma unroll
        for (int u = 0; u < 4; u++) v[u] = fmaxf(res[u], 0.f);
        *(float4*)(g_X0 + (size_t)n * 128 + base) = make_float4(v[0], v[1], v[2], v[3]);
        __half2 h[2];
        h[0] = __floats2half2_rn(v[0], v[1]);
        h[1] = __floats2half2_rn(v[2], v[3]);
        *(uint2*)(g_XH + (size_t)n * 128 + base) = *(uint2*)h;
    } else if constexpr (MODE == 1) {
        __half2 h = __floats2half2_rn(fmaxf(res[0], 0.f), fmaxf(res[1], 0.f));
        *(__half2*)(g_XH + (size_t)n * 64 + base) = h;
    } else {
        float4 x0 = *(const float4*)(g_X0 + (size_t)n * 128 + base);
        float4 o;
        o.x = fmaxf(res[0] + x0.x, 0.f);
        o.y = fmaxf(res[1] + x0.y, 0.f);
        o.z = fmaxf(res[2] + x0.z, 0.f);
        o.w = fmaxf(res[3] + x0.w, 0.f);
        *(float4*)(out + (size_t)n * 128 + base) = o;
    }
}

// ---------------------------------------------------------------------------
extern "C" void kernel_launch(void* const* d_in, const int* in_sizes, int n_in,
                              void* d_out, int out_size) {
    const float* x   = (const float*)d_in[0];
    const int*   e0  = (const int*)d_in[1];
    const int*   e1  = (const int*)d_in[2];
    const int*   e2  = (const int*)d_in[3];
    // d_in[4] = batch (unused)
    const float* wq0 = (const float*)d_in[5],  *bq0 = (const float*)d_in[6];
    const float* wk0 = (const float*)d_in[7],  *bk0 = (const float*)d_in[8];
    const float* wv0 = (const float*)d_in[9],  *bv0 = (const float*)d_in[10];
    const float* wq1 = (const float*)d_in[11], *bq1 = (const float*)d_in[12];
    const float* wk1 = (const float*)d_in[13], *bk1 = (const float*)d_in[14];
    const float* wv1 = (const float*)d_in[15], *bv1 = (const float*)d_in[16];
    const float* wq2 = (const float*)d_in[17], *bq2 = (const float*)d_in[18];
    const float* wk2 = (const float*)d_in[19], *bk2 = (const float*)d_in[20];
    const float* wv2 = (const float*)d_in[21], *bv2 = (const float*)d_in[22];
    float* out = (float*)d_out;

    int N  = in_sizes[0] / 128;   // 50000
    int E  = in_sizes[1] / 2;     // 500000

    __half* pXH = nullptr;
    cudaGetSymbolAddress((void**)&pXH, g_XH);

    constexpr int SMEM128 = 2 * 128 * 136 * 2 + 128 * 136 * 2;  // 104448
    constexpr int SMEM64  = 2 * 128 * 72 * 2  + 64 * 136 * 2;   // 54272

    const float KS16 = 0.25f;                 // 1/sqrt(16)
    const float KS8  = 0.35355339059327373f;  // 1/sqrt(8)

    static cudaStream_t s2 = nullptr;
    static cudaEvent_t evFork = nullptr, evJoin = nullptr;
    if (s2 == nullptr) {
        cudaFuncSetAttribute(gemm_v3_kernel<128>,
                             cudaFuncAttributeMaxDynamicSharedMemorySize, SMEM128);
        cudaFuncSetAttribute(gemm_v3_kernel<64>,
                             cudaFuncAttributeMaxDynamicSharedMemorySize, SMEM64);
        cudaStreamCreateWithFlags(&s2, cudaStreamNonBlocking);
        cudaEventCreateWithFlags(&evFork, cudaEventDisableTiming);
        cudaEventCreateWithFlags(&evJoin, cudaEventDisableTiming);
    }

    // ---- fork: edge sorts on side stream ----
    cudaEventRecord(evFork, 0);
    cudaStreamWaitEvent(s2, evFork, 0);
    {
        dim3 ge((E + 255) / 256, 3);
        dim3 gn((NN + 255) / 256, 3);
        zero3_kernel<<<(3 * NN + 255) / 256, 256, 0, s2>>>();
        hist3_kernel<<<ge, 256, 0, s2>>>(e0, e1, e2, E);
        scan1_kernel<<<gn, 256, 0, s2>>>();
        scan2_kernel<<<dim3(1, 3), 256, 0, s2>>>((NN + 255) / 256);
        scan3_kernel<<<gn, 256, 0, s2>>>();
        scatter3_kernel<<<ge, 256, 0, s2>>>(e0, e1, e2, E);
    }
    cudaEventRecord(evJoin, s2);

    // ---- main stream: convert + build all weights ----
    convert_x_kernel<<<(N * 128 + 255) / 256, 256>>>(x, N * 128);
    build_w_kernel<<<(128 * 768 + 255) / 256, 256>>>(wq0, wk0, wv0, bq0, bk0, bv0, 128, 128, 0, KS16);
    build_w_kernel<<<(128 * 384 + 255) / 256, 256>>>(wq1, wk1, wv1, bq1, bk1, bv1, 128, 64, 1, KS8);
    build_w_kernel<<<(64 * 768 + 255) / 256, 256>>>(wq2, wk2, wv2, bq2, bk2, bv2, 64, 128, 2, KS16);

    int aggGrid = (N * 32 + 255) / 256;

    // ---- Layer 0: C=128, O=128, M=768 ----
    gemm_v3_kernel<128><<<dim3(6, 49), 256, SMEM128>>>(pXH, N, 768, 0);
    cudaStreamWaitEvent(0, evJoin, 0);
    agg_kernel<128, 16, 0><<<aggGrid, 256>>>(nullptr, N, 0);

    // ---- Layer 1: C=128, O=64, M=384 ----
    gemm_v3_kernel<128><<<dim3(3, 98), 256, SMEM128>>>(pXH, N, 384, 1);
    agg_kernel<64, 8, 1><<<aggGrid, 256>>>(nullptr, N, 1);

    // ---- Layer 2: C=64, O=128, M=768 ----
    gemm_v3_kernel<64><<<dim3(6, 49), 256, SMEM64>>>(pXH, N, 768, 2);
    agg_kernel<128, 16, 2><<<aggGrid, 256>>>(out, N, 2);
}